// round 14
// baseline (speedup 1.0000x reference)
#include <cuda_runtime.h>
#include <cuda_bf16.h>

#define BQ 8
#define NQ 8192
#define MK 2048
#define CC 256
#define EPSW 1e-8f
#define GRID 8
#define NCELL (GRID*GRID*GRID)   // 512
#define CELLH 0.125f

// Scratch
__device__ float4 g_pts[BQ * MK];              // binned known points (x,y,z,idx)
__device__ int    g_cellstart[BQ][NCELL + 1];  // known-point cell offsets
__device__ float4 g_qpts[BQ * NQ];             // binned queries (x,y,z,idx)
__device__ float4 g_wp[BQ * NQ];               // (w0,w1,i0|i1<<16,i2)

typedef unsigned long long u64t;
__device__ __forceinline__ u64t fma2(u64t a, u64t b, u64t c) {
    u64t d; asm("fma.rn.f32x2 %0, %1, %2, %3;" : "=l"(d) : "l"(a), "l"(b), "l"(c));
    return d;
}
__device__ __forceinline__ u64t mul2(u64t a, u64t b) {
    u64t d; asm("mul.rn.f32x2 %0, %1, %2;" : "=l"(d) : "l"(a), "l"(b));
    return d;
}
__device__ __forceinline__ u64t pack2(float lo, float hi) {
    u64t d; asm("mov.b64 %0, {%1, %2};" : "=l"(d) : "f"(lo), "f"(hi));
    return d;
}
__device__ __forceinline__ void unpack2(u64t v, float& lo, float& hi) {
    asm("mov.b64 {%0, %1}, %2;" : "=f"(lo), "=f"(hi) : "l"(v));
}

__device__ __forceinline__ int cell_of(float x, float y, float z) {
    int cx = min(GRID - 1, max(0, (int)(x * (float)GRID)));
    int cy = min(GRID - 1, max(0, (int)(y * (float)GRID)));
    int cz = min(GRID - 1, max(0, (int)(z * (float)GRID)));
    return (cz * GRID + cy) * GRID + cx;
}

// ---------------------------------------------------------------------------
// Kernel A: fused counting sort (known pts -> g_pts; queries -> g_qpts).
// Scatter order within a cell is nondeterministic — safe because the NN
// insert is lexicographic (order-independent).
// ---------------------------------------------------------------------------
__global__ void __launch_bounds__(512) bin_kernel(
    const float* __restrict__ known,     // (B, M, 3)
    const float* __restrict__ unknown)   // (B, N, 3)
{
    __shared__ int hist[NCELL];
    __shared__ int wsum[16];

    const int b = blockIdx.x;
    const int role = blockIdx.y;
    const int t = threadIdx.x;
    const int lane = t & 31, warp = t >> 5;

    hist[t] = 0;
    __syncthreads();

    if (role == 0) {
        const float* kb = known + (size_t)b * MK * 3;
#pragma unroll
        for (int k = 0; k < MK / 512; k++) {
            int m = k * 512 + t;
            atomicAdd(&hist[cell_of(kb[m*3], kb[m*3+1], kb[m*3+2])], 1);
        }
    } else {
        const float* ub = unknown + (size_t)b * NQ * 3;
#pragma unroll
        for (int k = 0; k < NQ / 512; k++) {
            int m = k * 512 + t;
            atomicAdd(&hist[cell_of(ub[m*3], ub[m*3+1], ub[m*3+2])], 1);
        }
    }
    __syncthreads();

    // block-wide exclusive scan of hist[512]
    int v = hist[t];
    int incl = v;
#pragma unroll
    for (int off = 1; off < 32; off <<= 1) {
        int u = __shfl_up_sync(0xFFFFFFFFu, incl, off);
        if (lane >= off) incl += u;
    }
    if (lane == 31) wsum[warp] = incl;
    __syncthreads();
    if (t < 16) {
        int w = wsum[t];
        int vv = w;
#pragma unroll
        for (int off = 1; off < 16; off <<= 1) {
            int u = __shfl_up_sync(0x0000FFFFu, vv, off);
            if (t >= off) vv += u;
        }
        wsum[t] = vv - w;
    }
    __syncthreads();
    int excl = wsum[warp] + incl - v;

    if (role == 0) {
        g_cellstart[b][t] = excl;
        if (t == 0) g_cellstart[b][NCELL] = MK;
    }
    __syncthreads();
    hist[t] = excl;          // scatter cursor
    __syncthreads();

    if (role == 0) {
        const float* kb = known + (size_t)b * MK * 3;
#pragma unroll
        for (int k = 0; k < MK / 512; k++) {
            int m = k * 512 + t;
            float x = kb[m*3], y = kb[m*3+1], z = kb[m*3+2];
            int pos = atomicAdd(&hist[cell_of(x, y, z)], 1);
            g_pts[(size_t)b * MK + pos] = make_float4(x, y, z, __int_as_float(m));
        }
    } else {
        const float* ub = unknown + (size_t)b * NQ * 3;
#pragma unroll
        for (int k = 0; k < NQ / 512; k++) {
            int m = k * 512 + t;
            float x = ub[m*3], y = ub[m*3+1], z = ub[m*3+2];
            int pos = atomicAdd(&hist[cell_of(x, y, z)], 1);
            g_qpts[(size_t)b * NQ + pos] = make_float4(x, y, z, __int_as_float(m));
        }
    }
}

// ---------------------------------------------------------------------------
// Kernel B: three_nn. Warp = 32 consecutive SORTED queries (full lanes);
// warp-reduced cell bounding box -> warp-uniform expanding-box search.
// Rows of cells are contiguous in the point array -> flat 4-point-batched
// loops (MLP). EXACT d^2; lexicographic (d2, idx) insert.
// Stop when all lanes have d3^2 <= (s*CELLH)^2 after box radius s.
// Block 128 (4 warps), grid (NQ/128, BQ) = 512 blocks.
// ---------------------------------------------------------------------------
__global__ void __launch_bounds__(128) nn_kernel()
{
    __shared__ float4 spts[MK];          // 32 KB
    __shared__ int    sstart[NCELL + 1];

    const int b = blockIdx.y;
    for (int i = threadIdx.x; i < MK; i += 128)
        spts[i] = g_pts[(size_t)b * MK + i];
    for (int i = threadIdx.x; i < NCELL + 1; i += 128)
        sstart[i] = g_cellstart[b][i];
    __syncthreads();

    const int qslot = blockIdx.x * 128 + threadIdx.x;
    float4 Q = g_qpts[(size_t)b * NQ + qslot];
    const float ux = Q.x, uy = Q.y, uz = Q.z;
    const int n = __float_as_int(Q.w);
    const int cx = min(GRID - 1, max(0, (int)(ux * (float)GRID)));
    const int cy = min(GRID - 1, max(0, (int)(uy * (float)GRID)));
    const int cz = min(GRID - 1, max(0, (int)(uz * (float)GRID)));

    // warp-wide cell bounding box
    int mnx = cx, mxx = cx, mny = cy, mxy = cy, mnz = cz, mxz = cz;
#pragma unroll
    for (int off = 16; off; off >>= 1) {
        mnx = min(mnx, __shfl_xor_sync(0xFFFFFFFFu, mnx, off));
        mxx = max(mxx, __shfl_xor_sync(0xFFFFFFFFu, mxx, off));
        mny = min(mny, __shfl_xor_sync(0xFFFFFFFFu, mny, off));
        mxy = max(mxy, __shfl_xor_sync(0xFFFFFFFFu, mxy, off));
        mnz = min(mnz, __shfl_xor_sync(0xFFFFFFFFu, mnz, off));
        mxz = max(mxz, __shfl_xor_sync(0xFFFFFFFFu, mxz, off));
    }

    float d0 = 1e30f, d1 = 1e30f, d2v = 1e30f;
    int   i0 = 0x7FFFFFFF, i1 = 0x7FFFFFFF, i2 = 0x7FFFFFFF;

    auto insert = [&](float d2, int m) {
        bool c0 = (d2 < d0) || (d2 == d0 && m < i0);
        bool c1 = (d2 < d1) || (d2 == d1 && m < i1);
        bool c2 = (d2 < d2v) || (d2 == d2v && m < i2);
        float t0 = c0 ? d2 : d0;
        float t1 = c0 ? d0 : (c1 ? d2 : d1);
        float t2 = c1 ? d1 : (c2 ? d2 : d2v);
        int   j0 = c0 ? m  : i0;
        int   j1 = c0 ? i0 : (c1 ? m  : i1);
        int   j2 = c1 ? i1 : (c2 ? m  : i2);
        d0 = t0; d1 = t1; d2v = t2;
        i0 = j0; i1 = j1; i2 = j2;
    };

    auto d2_of = [&](float4 P) {
        float dx = P.x - ux, dy = P.y - uy, dz = P.z - uz;
        return fmaf(dx, dx, fmaf(dy, dy, dz * dz));
    };

    // flat point segment [p0, p1), 4-point batched
    auto segment = [&](int p, int pend) {
        for (; p + 4 <= pend; p += 4) {
            float4 P0 = spts[p], P1 = spts[p+1], P2 = spts[p+2], P3 = spts[p+3];
            float e0 = d2_of(P0), e1 = d2_of(P1), e2 = d2_of(P2), e3 = d2_of(P3);
            insert(e0, __float_as_int(P0.w));
            insert(e1, __float_as_int(P1.w));
            insert(e2, __float_as_int(P2.w));
            insert(e3, __float_as_int(P3.w));
        }
        for (; p < pend; p++) {
            float4 P = spts[p];
            insert(d2_of(P), __float_as_int(P.w));
        }
    };

    auto row = [&](int z, int y, int xl, int xr) {
        if (xl > xr) return;
        int base = (z * GRID + y) * GRID;
        segment(sstart[base + xl], sstart[base + xr + 1]);
    };

    int pxlo = 1, pxhi = 0, pylo = 1, pyhi = 0, pzlo = 1, pzhi = 0; // empty

#pragma unroll 1
    for (int s = 1; s <= GRID - 1; s++) {
        int xlo = max(mnx - s, 0), xhi = min(mxx + s, GRID - 1);
        int ylo = max(mny - s, 0), yhi = min(mxy + s, GRID - 1);
        int zlo = max(mnz - s, 0), zhi = min(mxz + s, GRID - 1);

        for (int z = zlo; z <= zhi; z++) {
            bool zin = (z >= pzlo && z <= pzhi);
            for (int y = ylo; y <= yhi; y++) {
                if (zin && y >= pylo && y <= pyhi) {
                    // exclude previously processed x-range
                    row(z, y, xlo, pxlo - 1);
                    row(z, y, pxhi + 1, xhi);
                } else {
                    row(z, y, xlo, xhi);
                }
            }
        }

        // done? every unprocessed point is >= s*CELLH away from every query
        float thr = CELLH * (float)s;
        if (__all_sync(0xFFFFFFFFu, d2v <= thr * thr)) break;
        if (xlo == 0 && xhi == GRID - 1 && ylo == 0 && yhi == GRID - 1 &&
            zlo == 0 && zhi == GRID - 1) break;   // whole grid processed

        pxlo = xlo; pxhi = xhi; pylo = ylo; pyhi = yhi; pzlo = zlo; pzhi = zhi;
    }

    const float r0 = 1.0f / (d0 + EPSW);
    const float r1 = 1.0f / (d1 + EPSW);
    const float r2 = 1.0f / (d2v + EPSW);
    const float s  = 1.0f / (r0 + r1 + r2);
    g_wp[(size_t)b * NQ + n] =
        make_float4(r0 * s, r1 * s,
                    __int_as_float(i0 | (i1 << 16)),
                    __int_as_float(i2));
}

// ---------------------------------------------------------------------------
// Kernel C: three_interpolate (unchanged — measured local floor ~33.5 us).
// ---------------------------------------------------------------------------
#define CG 4

__global__ void __launch_bounds__(256) interp_kernel(
    const float* __restrict__ feats,     // (B, C, M)
    float* __restrict__ out)             // (B, C, N)
{
    __shared__ float rowsT[MK * CG];     // 32 KB

    const int b  = blockIdx.y;
    const int c0 = blockIdx.x * CG;

    {
        const float* fp = feats + ((size_t)b * CC + c0) * MK;
#pragma unroll
        for (int it = 0; it < MK / 256; it++) {
            const int m = it * 256 + threadIdx.x;
            float a  = fp[m];
            float bb = fp[MK + m];
            float c  = fp[2 * MK + m];
            float d  = fp[3 * MK + m];
            *(float4*)&rowsT[m * 4] = make_float4(a, bb, c, d);
        }
    }
    __syncthreads();

    const float4* wp = (const float4*)&g_wp[(size_t)b * NQ];
    float* outp = out + ((size_t)b * CC + c0) * NQ;

    for (int it = 0; it < NQ / 1024; it++) {   // 8 iters
        const int n0 = it * 1024 + threadIdx.x * 4;

        float4 W0 = wp[n0 + 0];
        float4 W1 = wp[n0 + 1];
        float4 W2 = wp[n0 + 2];
        float4 W3 = wp[n0 + 3];

        int j[12];
        {
            unsigned pk0 = __float_as_uint(W0.z);
            unsigned pk1 = __float_as_uint(W1.z);
            unsigned pk2 = __float_as_uint(W2.z);
            unsigned pk3 = __float_as_uint(W3.z);
            j[0]  = pk0 & 0xFFFF; j[1]  = pk0 >> 16; j[2]  = __float_as_uint(W0.w);
            j[3]  = pk1 & 0xFFFF; j[4]  = pk1 >> 16; j[5]  = __float_as_uint(W1.w);
            j[6]  = pk2 & 0xFFFF; j[7]  = pk2 >> 16; j[8]  = __float_as_uint(W2.w);
            j[9]  = pk3 & 0xFFFF; j[10] = pk3 >> 16; j[11] = __float_as_uint(W3.w);
        }

        ulonglong2 f[12];
#pragma unroll
        for (int t = 0; t < 12; t++)
            f[t] = *(const ulonglong2*)&rowsT[j[t] * 4];

        float vq[4][4];
        const float4 Wv[4] = { W0, W1, W2, W3 };
#pragma unroll
        for (int q = 0; q < 4; q++) {
            float w0 = Wv[q].x, w1 = Wv[q].y;
            float w2 = 1.0f - w0 - w1;
            u64t w0p = pack2(w0, w0);
            u64t w1p = pack2(w1, w1);
            u64t w2p = pack2(w2, w2);
            u64t lo = fma2(w0p, f[3*q].x, fma2(w1p, f[3*q+1].x, mul2(w2p, f[3*q+2].x)));
            u64t hi = fma2(w0p, f[3*q].y, fma2(w1p, f[3*q+1].y, mul2(w2p, f[3*q+2].y)));
            unpack2(lo, vq[q][0], vq[q][1]);
            unpack2(hi, vq[q][2], vq[q][3]);
        }

#pragma unroll
        for (int c = 0; c < CG; c++) {
            float4 v = make_float4(vq[0][c], vq[1][c], vq[2][c], vq[3][c]);
            *(float4*)(outp + (size_t)c * NQ + n0) = v;
        }
    }
}

// ---------------------------------------------------------------------------
// Launch
// ---------------------------------------------------------------------------
extern "C" void kernel_launch(void* const* d_in, const int* in_sizes, int n_in,
                              void* d_out, int out_size)
{
    const float* unknown = (const float*)d_in[0];   // (8, 8192, 3)
    const float* known   = (const float*)d_in[1];   // (8, 2048, 3)
    const float* feats   = (const float*)d_in[2];   // (8, 256, 2048)
    float* out = (float*)d_out;                     // (8, 256, 8192)

    bin_kernel<<<dim3(BQ, 2), 512>>>(known, unknown);

    nn_kernel<<<dim3(NQ / 128, BQ), 128>>>();

    dim3 g2(CC / CG, BQ);
    interp_kernel<<<g2, 256>>>(feats, out);
}

// round 15
// speedup vs baseline: 2.9023x; 2.9023x over previous
#include <cuda_runtime.h>
#include <cuda_bf16.h>

#define BQ 8
#define NQ 8192
#define MK 2048
#define CC 256
#define EPSW 1e-8f
#define GRID 8
#define NCELL (GRID*GRID*GRID)   // 512
#define CELLH 0.125f

// Scratch
__device__ float4 g_pts[BQ * MK];              // binned known points (x,y,z,idx)
__device__ int    g_cellstart[BQ][NCELL + 1];  // known-point cell offsets
__device__ float4 g_qpts[BQ * NQ];             // binned queries (x,y,z,idx)
__device__ float4 g_wp[BQ * NQ];               // (w0,w1,i0|i1<<16,i2)

typedef unsigned long long u64t;
__device__ __forceinline__ u64t fma2(u64t a, u64t b, u64t c) {
    u64t d; asm("fma.rn.f32x2 %0, %1, %2, %3;" : "=l"(d) : "l"(a), "l"(b), "l"(c));
    return d;
}
__device__ __forceinline__ u64t mul2(u64t a, u64t b) {
    u64t d; asm("mul.rn.f32x2 %0, %1, %2;" : "=l"(d) : "l"(a), "l"(b));
    return d;
}
__device__ __forceinline__ u64t pack2(float lo, float hi) {
    u64t d; asm("mov.b64 %0, {%1, %2};" : "=l"(d) : "f"(lo), "f"(hi));
    return d;
}
__device__ __forceinline__ void unpack2(u64t v, float& lo, float& hi) {
    asm("mov.b64 {%0, %1}, %2;" : "=f"(lo), "=f"(hi) : "l"(v));
}

__device__ __forceinline__ int cell_of(float x, float y, float z) {
    int cx = min(GRID - 1, max(0, (int)(x * (float)GRID)));
    int cy = min(GRID - 1, max(0, (int)(y * (float)GRID)));
    int cz = min(GRID - 1, max(0, (int)(z * (float)GRID)));
    return (cz * GRID + cy) * GRID + cx;
}

// ---------------------------------------------------------------------------
// Kernel A: fused counting sort (known pts -> g_pts; queries -> g_qpts).
// Scatter order within a cell is nondeterministic — safe because the NN
// insert is lexicographic (order-independent).
// ---------------------------------------------------------------------------
__global__ void __launch_bounds__(512) bin_kernel(
    const float* __restrict__ known,     // (B, M, 3)
    const float* __restrict__ unknown)   // (B, N, 3)
{
    __shared__ int hist[NCELL];
    __shared__ int wsum[16];

    const int b = blockIdx.x;
    const int role = blockIdx.y;
    const int t = threadIdx.x;
    const int lane = t & 31, warp = t >> 5;

    hist[t] = 0;
    __syncthreads();

    if (role == 0) {
        const float* kb = known + (size_t)b * MK * 3;
#pragma unroll
        for (int k = 0; k < MK / 512; k++) {
            int m = k * 512 + t;
            atomicAdd(&hist[cell_of(kb[m*3], kb[m*3+1], kb[m*3+2])], 1);
        }
    } else {
        const float* ub = unknown + (size_t)b * NQ * 3;
#pragma unroll
        for (int k = 0; k < NQ / 512; k++) {
            int m = k * 512 + t;
            atomicAdd(&hist[cell_of(ub[m*3], ub[m*3+1], ub[m*3+2])], 1);
        }
    }
    __syncthreads();

    // block-wide exclusive scan of hist[512]
    int v = hist[t];
    int incl = v;
#pragma unroll
    for (int off = 1; off < 32; off <<= 1) {
        int u = __shfl_up_sync(0xFFFFFFFFu, incl, off);
        if (lane >= off) incl += u;
    }
    if (lane == 31) wsum[warp] = incl;
    __syncthreads();
    if (t < 16) {
        int w = wsum[t];
        int vv = w;
#pragma unroll
        for (int off = 1; off < 16; off <<= 1) {
            int u = __shfl_up_sync(0x0000FFFFu, vv, off);
            if (t >= off) vv += u;
        }
        wsum[t] = vv - w;
    }
    __syncthreads();
    int excl = wsum[warp] + incl - v;

    if (role == 0) {
        g_cellstart[b][t] = excl;
        if (t == 0) g_cellstart[b][NCELL] = MK;
    }
    __syncthreads();
    hist[t] = excl;          // scatter cursor
    __syncthreads();

    if (role == 0) {
        const float* kb = known + (size_t)b * MK * 3;
#pragma unroll
        for (int k = 0; k < MK / 512; k++) {
            int m = k * 512 + t;
            float x = kb[m*3], y = kb[m*3+1], z = kb[m*3+2];
            int pos = atomicAdd(&hist[cell_of(x, y, z)], 1);
            g_pts[(size_t)b * MK + pos] = make_float4(x, y, z, __int_as_float(m));
        }
    } else {
        const float* ub = unknown + (size_t)b * NQ * 3;
#pragma unroll
        for (int k = 0; k < NQ / 512; k++) {
            int m = k * 512 + t;
            float x = ub[m*3], y = ub[m*3+1], z = ub[m*3+2];
            int pos = atomicAdd(&hist[cell_of(x, y, z)], 1);
            g_qpts[(size_t)b * NQ + pos] = make_float4(x, y, z, __int_as_float(m));
        }
    }
}

// ---------------------------------------------------------------------------
// Kernel B: three_nn. Lanes = 32 consecutive SORTED queries (full
// utilization, 2-3 adjacent cells per warp -> near-lockstep loops, 2-3-way
// LDS address splits instead of 32). Each lane walks ITS OWN radius-1 cube
// + expanding Chebyshev shells (R12's proven-correct control flow).
// EXACT d^2; lexicographic (d2, idx) insert (order-independent; jax
// lower-index tie-break). Stop when d3^2 <= ((s-1)*CELLH)^2 before shell s.
// Block 128 (4 warps), grid (NQ/128, BQ) = 512 blocks.
// ---------------------------------------------------------------------------
__global__ void __launch_bounds__(128) nn_kernel()
{
    __shared__ float4 spts[MK];          // 32 KB
    __shared__ int    sstart[NCELL + 1];

    const int b = blockIdx.y;
    for (int i = threadIdx.x; i < MK; i += 128)
        spts[i] = g_pts[(size_t)b * MK + i];
    for (int i = threadIdx.x; i < NCELL + 1; i += 128)
        sstart[i] = g_cellstart[b][i];
    __syncthreads();

    const int qslot = blockIdx.x * 128 + threadIdx.x;
    float4 Q = g_qpts[(size_t)b * NQ + qslot];
    const float ux = Q.x, uy = Q.y, uz = Q.z;
    const int n = __float_as_int(Q.w);
    const int cx = min(GRID - 1, max(0, (int)(ux * (float)GRID)));
    const int cy = min(GRID - 1, max(0, (int)(uy * (float)GRID)));
    const int cz = min(GRID - 1, max(0, (int)(uz * (float)GRID)));

    float d0 = 1e30f, d1 = 1e30f, d2v = 1e30f;
    int   i0 = 0x7FFFFFFF, i1 = 0x7FFFFFFF, i2 = 0x7FFFFFFF;

    auto process_cell = [&](int c) {
        int s = sstart[c], e = sstart[c + 1];
        for (int p = s; p < e; p++) {
            float4 P = spts[p];
            float dx = P.x - ux, dy = P.y - uy, dz = P.z - uz;
            float d2 = fmaf(dx, dx, fmaf(dy, dy, dz * dz));
            int m = __float_as_int(P.w);
            bool c0 = (d2 < d0) || (d2 == d0 && m < i0);
            bool c1 = (d2 < d1) || (d2 == d1 && m < i1);
            bool c2 = (d2 < d2v) || (d2 == d2v && m < i2);
            float t0 = c0 ? d2 : d0;
            float t1 = c0 ? d0 : (c1 ? d2 : d1);
            float t2 = c1 ? d1 : (c2 ? d2 : d2v);
            int   j0 = c0 ? m  : i0;
            int   j1 = c0 ? i0 : (c1 ? m  : i1);
            int   j2 = c1 ? i1 : (c2 ? m  : i2);
            d0 = t0; d1 = t1; d2v = t2;
            i0 = j0; i1 = j1; i2 = j2;
        }
    };

    // radius-1: process the 3 contiguous x-runs per (z,y)
    {
        int zlo = max(cz - 1, 0), zhi = min(cz + 1, GRID - 1);
        int ylo = max(cy - 1, 0), yhi = min(cy + 1, GRID - 1);
        int xlo = max(cx - 1, 0), xhi = min(cx + 1, GRID - 1);
        for (int z = zlo; z <= zhi; z++)
            for (int y = ylo; y <= yhi; y++) {
                int base = (z * GRID + y) * GRID;
                int s = sstart[base + xlo], e = sstart[base + xhi + 1];
                for (int p = s; p < e; p++) {
                    float4 P = spts[p];
                    float dx = P.x - ux, dy = P.y - uy, dz = P.z - uz;
                    float d2 = fmaf(dx, dx, fmaf(dy, dy, dz * dz));
                    int m = __float_as_int(P.w);
                    bool c0 = (d2 < d0) || (d2 == d0 && m < i0);
                    bool c1 = (d2 < d1) || (d2 == d1 && m < i1);
                    bool c2 = (d2 < d2v) || (d2 == d2v && m < i2);
                    float t0 = c0 ? d2 : d0;
                    float t1 = c0 ? d0 : (c1 ? d2 : d1);
                    float t2 = c1 ? d1 : (c2 ? d2 : d2v);
                    int   j0 = c0 ? m  : i0;
                    int   j1 = c0 ? i0 : (c1 ? m  : i1);
                    int   j2 = c1 ? i1 : (c2 ? m  : i2);
                    d0 = t0; d1 = t1; d2v = t2;
                    i0 = j0; i1 = j1; i2 = j2;
                }
            }
    }

    // expanding Chebyshev shells until guaranteed
#pragma unroll 1
    for (int s2 = 2; s2 <= GRID - 1; s2++) {
        float thr = CELLH * (float)(s2 - 1);
        if (d2v <= thr * thr) break;
        int zlo = max(cz - s2, 0), zhi = min(cz + s2, GRID - 1);
        int ylo = max(cy - s2, 0), yhi = min(cy + s2, GRID - 1);
        int xlo = max(cx - s2, 0), xhi = min(cx + s2, GRID - 1);
        for (int z = zlo; z <= zhi; z++)
            for (int y = ylo; y <= yhi; y++)
                for (int x = xlo; x <= xhi; x++) {
                    int ch = max(abs(z - cz), max(abs(y - cy), abs(x - cx)));
                    if (ch != s2) continue;
                    process_cell((z * GRID + y) * GRID + x);
                }
    }

    const float r0 = 1.0f / (d0 + EPSW);
    const float r1 = 1.0f / (d1 + EPSW);
    const float r2 = 1.0f / (d2v + EPSW);
    const float s  = 1.0f / (r0 + r1 + r2);
    g_wp[(size_t)b * NQ + n] =
        make_float4(r0 * s, r1 * s,
                    __int_as_float(i0 | (i1 << 16)),
                    __int_as_float(i2));
}

// ---------------------------------------------------------------------------
// Kernel C: three_interpolate (unchanged — measured local floor ~33.5 us).
// ---------------------------------------------------------------------------
#define CG 4

__global__ void __launch_bounds__(256) interp_kernel(
    const float* __restrict__ feats,     // (B, C, M)
    float* __restrict__ out)             // (B, C, N)
{
    __shared__ float rowsT[MK * CG];     // 32 KB

    const int b  = blockIdx.y;
    const int c0 = blockIdx.x * CG;

    {
        const float* fp = feats + ((size_t)b * CC + c0) * MK;
#pragma unroll
        for (int it = 0; it < MK / 256; it++) {
            const int m = it * 256 + threadIdx.x;
            float a  = fp[m];
            float bb = fp[MK + m];
            float c  = fp[2 * MK + m];
            float d  = fp[3 * MK + m];
            *(float4*)&rowsT[m * 4] = make_float4(a, bb, c, d);
        }
    }
    __syncthreads();

    const float4* wp = (const float4*)&g_wp[(size_t)b * NQ];
    float* outp = out + ((size_t)b * CC + c0) * NQ;

    for (int it = 0; it < NQ / 1024; it++) {   // 8 iters
        const int n0 = it * 1024 + threadIdx.x * 4;

        float4 W0 = wp[n0 + 0];
        float4 W1 = wp[n0 + 1];
        float4 W2 = wp[n0 + 2];
        float4 W3 = wp[n0 + 3];

        int j[12];
        {
            unsigned pk0 = __float_as_uint(W0.z);
            unsigned pk1 = __float_as_uint(W1.z);
            unsigned pk2 = __float_as_uint(W2.z);
            unsigned pk3 = __float_as_uint(W3.z);
            j[0]  = pk0 & 0xFFFF; j[1]  = pk0 >> 16; j[2]  = __float_as_uint(W0.w);
            j[3]  = pk1 & 0xFFFF; j[4]  = pk1 >> 16; j[5]  = __float_as_uint(W1.w);
            j[6]  = pk2 & 0xFFFF; j[7]  = pk2 >> 16; j[8]  = __float_as_uint(W2.w);
            j[9]  = pk3 & 0xFFFF; j[10] = pk3 >> 16; j[11] = __float_as_uint(W3.w);
        }

        ulonglong2 f[12];
#pragma unroll
        for (int t = 0; t < 12; t++)
            f[t] = *(const ulonglong2*)&rowsT[j[t] * 4];

        float vq[4][4];
        const float4 Wv[4] = { W0, W1, W2, W3 };
#pragma unroll
        for (int q = 0; q < 4; q++) {
            float w0 = Wv[q].x, w1 = Wv[q].y;
            float w2 = 1.0f - w0 - w1;
            u64t w0p = pack2(w0, w0);
            u64t w1p = pack2(w1, w1);
            u64t w2p = pack2(w2, w2);
            u64t lo = fma2(w0p, f[3*q].x, fma2(w1p, f[3*q+1].x, mul2(w2p, f[3*q+2].x)));
            u64t hi = fma2(w0p, f[3*q].y, fma2(w1p, f[3*q+1].y, mul2(w2p, f[3*q+2].y)));
            unpack2(lo, vq[q][0], vq[q][1]);
            unpack2(hi, vq[q][2], vq[q][3]);
        }

#pragma unroll
        for (int c = 0; c < CG; c++) {
            float4 v = make_float4(vq[0][c], vq[1][c], vq[2][c], vq[3][c]);
            *(float4*)(outp + (size_t)c * NQ + n0) = v;
        }
    }
}

// ---------------------------------------------------------------------------
// Launch
// ---------------------------------------------------------------------------
extern "C" void kernel_launch(void* const* d_in, const int* in_sizes, int n_in,
                              void* d_out, int out_size)
{
    const float* unknown = (const float*)d_in[0];   // (8, 8192, 3)
    const float* known   = (const float*)d_in[1];   // (8, 2048, 3)
    const float* feats   = (const float*)d_in[2];   // (8, 256, 2048)
    float* out = (float*)d_out;                     // (8, 256, 8192)

    bin_kernel<<<dim3(BQ, 2), 512>>>(known, unknown);

    nn_kernel<<<dim3(NQ / 128, BQ), 128>>>();

    dim3 g2(CC / CG, BQ);
    interp_kernel<<<g2, 256>>>(feats, out);
}

// round 16
// speedup vs baseline: 3.5657x; 1.2286x over previous
#include <cuda_runtime.h>
#include <cuda_bf16.h>

#define BQ 8
#define NQ 8192
#define MK 2048
#define CC 256
#define EPSW 1e-8f
#define GRID 8
#define NCELL (GRID*GRID*GRID)   // 512
#define CELLH 0.125f

// Scratch
__device__ float4 g_pts[BQ * MK];              // binned known points (x,y,z,idx)
__device__ int    g_cellstart[BQ][NCELL + 1];  // known-point cell offsets
__device__ float4 g_qpts[BQ * NQ];             // binned queries (x,y,z,idx)
__device__ float4 g_wp[BQ * NQ];               // (w0,w1,i0|i1<<16,i2)

typedef unsigned long long u64t;
__device__ __forceinline__ u64t fma2(u64t a, u64t b, u64t c) {
    u64t d; asm("fma.rn.f32x2 %0, %1, %2, %3;" : "=l"(d) : "l"(a), "l"(b), "l"(c));
    return d;
}
__device__ __forceinline__ u64t mul2(u64t a, u64t b) {
    u64t d; asm("mul.rn.f32x2 %0, %1, %2;" : "=l"(d) : "l"(a), "l"(b));
    return d;
}
__device__ __forceinline__ u64t pack2(float lo, float hi) {
    u64t d; asm("mov.b64 %0, {%1, %2};" : "=l"(d) : "f"(lo), "f"(hi));
    return d;
}
__device__ __forceinline__ void unpack2(u64t v, float& lo, float& hi) {
    asm("mov.b64 {%0, %1}, %2;" : "=f"(lo), "=f"(hi) : "l"(v));
}

__device__ __forceinline__ int cell_of(float x, float y, float z) {
    int cx = min(GRID - 1, max(0, (int)(x * (float)GRID)));
    int cy = min(GRID - 1, max(0, (int)(y * (float)GRID)));
    int cz = min(GRID - 1, max(0, (int)(z * (float)GRID)));
    return (cz * GRID + cy) * GRID + cx;
}

// ---------------------------------------------------------------------------
// Kernel A: fused counting sort (known pts -> g_pts; queries -> g_qpts).
// Scatter order within a cell is nondeterministic — safe because the NN
// insert is lexicographic (order-independent).
// ---------------------------------------------------------------------------
__global__ void __launch_bounds__(512) bin_kernel(
    const float* __restrict__ known,     // (B, M, 3)
    const float* __restrict__ unknown)   // (B, N, 3)
{
    __shared__ int hist[NCELL];
    __shared__ int wsum[16];

    const int b = blockIdx.x;
    const int role = blockIdx.y;
    const int t = threadIdx.x;
    const int lane = t & 31, warp = t >> 5;

    hist[t] = 0;
    __syncthreads();

    if (role == 0) {
        const float* kb = known + (size_t)b * MK * 3;
#pragma unroll
        for (int k = 0; k < MK / 512; k++) {
            int m = k * 512 + t;
            atomicAdd(&hist[cell_of(kb[m*3], kb[m*3+1], kb[m*3+2])], 1);
        }
    } else {
        const float* ub = unknown + (size_t)b * NQ * 3;
#pragma unroll
        for (int k = 0; k < NQ / 512; k++) {
            int m = k * 512 + t;
            atomicAdd(&hist[cell_of(ub[m*3], ub[m*3+1], ub[m*3+2])], 1);
        }
    }
    __syncthreads();

    // block-wide exclusive scan of hist[512]
    int v = hist[t];
    int incl = v;
#pragma unroll
    for (int off = 1; off < 32; off <<= 1) {
        int u = __shfl_up_sync(0xFFFFFFFFu, incl, off);
        if (lane >= off) incl += u;
    }
    if (lane == 31) wsum[warp] = incl;
    __syncthreads();
    if (t < 16) {
        int w = wsum[t];
        int vv = w;
#pragma unroll
        for (int off = 1; off < 16; off <<= 1) {
            int u = __shfl_up_sync(0x0000FFFFu, vv, off);
            if (t >= off) vv += u;
        }
        wsum[t] = vv - w;
    }
    __syncthreads();
    int excl = wsum[warp] + incl - v;

    if (role == 0) {
        g_cellstart[b][t] = excl;
        if (t == 0) g_cellstart[b][NCELL] = MK;
    }
    __syncthreads();
    hist[t] = excl;          // scatter cursor
    __syncthreads();

    if (role == 0) {
        const float* kb = known + (size_t)b * MK * 3;
#pragma unroll
        for (int k = 0; k < MK / 512; k++) {
            int m = k * 512 + t;
            float x = kb[m*3], y = kb[m*3+1], z = kb[m*3+2];
            int pos = atomicAdd(&hist[cell_of(x, y, z)], 1);
            g_pts[(size_t)b * MK + pos] = make_float4(x, y, z, __int_as_float(m));
        }
    } else {
        const float* ub = unknown + (size_t)b * NQ * 3;
#pragma unroll
        for (int k = 0; k < NQ / 512; k++) {
            int m = k * 512 + t;
            float x = ub[m*3], y = ub[m*3+1], z = ub[m*3+2];
            int pos = atomicAdd(&hist[cell_of(x, y, z)], 1);
            g_qpts[(size_t)b * NQ + pos] = make_float4(x, y, z, __int_as_float(m));
        }
    }
}

// ---------------------------------------------------------------------------
// Kernel B: three_nn. Lanes = 32 consecutive SORTED queries; each lane walks
// its radius-1 cube then expanding shells. STOPPING RULE: exact guard —
// after processing box [xlo..xhi]x[ylo..yhi]x[zlo..zhi], every unprocessed
// point is >= min over non-clipped faces of (distance from query to face
// plane). Domain-edge faces are infinite (no cells beyond). Stop when
// d3^2 <= guard^2. This is exact (no approximation), and it removes the
// spurious shell-2 passes that dominated R15 (esp. boundary queries).
// EXACT d^2; lexicographic (d2, idx) insert (order-independent; jax
// lower-index tie-break). Block 128, grid (NQ/128, BQ) = 512 blocks.
// ---------------------------------------------------------------------------
__global__ void __launch_bounds__(128) nn_kernel()
{
    __shared__ float4 spts[MK];          // 32 KB
    __shared__ int    sstart[NCELL + 1];

    const int b = blockIdx.y;
    for (int i = threadIdx.x; i < MK; i += 128)
        spts[i] = g_pts[(size_t)b * MK + i];
    for (int i = threadIdx.x; i < NCELL + 1; i += 128)
        sstart[i] = g_cellstart[b][i];
    __syncthreads();

    const int qslot = blockIdx.x * 128 + threadIdx.x;
    float4 Q = g_qpts[(size_t)b * NQ + qslot];
    const float ux = Q.x, uy = Q.y, uz = Q.z;
    const int n = __float_as_int(Q.w);
    const int cx = min(GRID - 1, max(0, (int)(ux * (float)GRID)));
    const int cy = min(GRID - 1, max(0, (int)(uy * (float)GRID)));
    const int cz = min(GRID - 1, max(0, (int)(uz * (float)GRID)));

    float d0 = 1e30f, d1 = 1e30f, d2v = 1e30f;
    int   i0 = 0x7FFFFFFF, i1 = 0x7FFFFFFF, i2 = 0x7FFFFFFF;

    auto insert = [&](float d2, int m) {
        bool c0 = (d2 < d0) || (d2 == d0 && m < i0);
        bool c1 = (d2 < d1) || (d2 == d1 && m < i1);
        bool c2 = (d2 < d2v) || (d2 == d2v && m < i2);
        float t0 = c0 ? d2 : d0;
        float t1 = c0 ? d0 : (c1 ? d2 : d1);
        float t2 = c1 ? d1 : (c2 ? d2 : d2v);
        int   j0 = c0 ? m  : i0;
        int   j1 = c0 ? i0 : (c1 ? m  : i1);
        int   j2 = c1 ? i1 : (c2 ? m  : i2);
        d0 = t0; d1 = t1; d2v = t2;
        i0 = j0; i1 = j1; i2 = j2;
    };

    auto seg = [&](int p, int pend) {
        // 2-point batched for a little MLP
        for (; p + 2 <= pend; p += 2) {
            float4 P0 = spts[p], P1 = spts[p + 1];
            float dx0 = P0.x - ux, dy0 = P0.y - uy, dz0 = P0.z - uz;
            float dx1 = P1.x - ux, dy1 = P1.y - uy, dz1 = P1.z - uz;
            float e0 = fmaf(dx0, dx0, fmaf(dy0, dy0, dz0 * dz0));
            float e1 = fmaf(dx1, dx1, fmaf(dy1, dy1, dz1 * dz1));
            insert(e0, __float_as_int(P0.w));
            insert(e1, __float_as_int(P1.w));
        }
        if (p < pend) {
            float4 P = spts[p];
            float dx = P.x - ux, dy = P.y - uy, dz = P.z - uz;
            insert(fmaf(dx, dx, fmaf(dy, dy, dz * dz)), __float_as_int(P.w));
        }
    };

    // exact guard^2 for processed box [xl..xh]x[yl..yh]x[zl..zh]
    auto guard2 = [&](int xl, int xh, int yl, int yh, int zl, int zh) {
        float g = 1e15f;
        g = fminf(g, (xl > 0)        ? ux - (float)xl * CELLH        : 1e15f);
        g = fminf(g, (xh < GRID - 1) ? (float)(xh + 1) * CELLH - ux  : 1e15f);
        g = fminf(g, (yl > 0)        ? uy - (float)yl * CELLH        : 1e15f);
        g = fminf(g, (yh < GRID - 1) ? (float)(yh + 1) * CELLH - uy  : 1e15f);
        g = fminf(g, (zl > 0)        ? uz - (float)zl * CELLH        : 1e15f);
        g = fminf(g, (zh < GRID - 1) ? (float)(zh + 1) * CELLH - uz  : 1e15f);
        return g * g;
    };

    // radius-1 cube: contiguous x-run per (z,y)
    int xlo = max(cx - 1, 0), xhi = min(cx + 1, GRID - 1);
    int ylo = max(cy - 1, 0), yhi = min(cy + 1, GRID - 1);
    int zlo = max(cz - 1, 0), zhi = min(cz + 1, GRID - 1);
    for (int z = zlo; z <= zhi; z++)
        for (int y = ylo; y <= yhi; y++) {
            int base = (z * GRID + y) * GRID;
            seg(sstart[base + xlo], sstart[base + xhi + 1]);
        }

    // expanding shells with exact guard
#pragma unroll 1
    for (int s2 = 2; s2 <= GRID - 1; s2++) {
        if (d2v <= guard2(xlo, xhi, ylo, yhi, zlo, zhi)) break;
        int nxlo = max(cx - s2, 0), nxhi = min(cx + s2, GRID - 1);
        int nylo = max(cy - s2, 0), nyhi = min(cy + s2, GRID - 1);
        int nzlo = max(cz - s2, 0), nzhi = min(cz + s2, GRID - 1);
        for (int z = nzlo; z <= nzhi; z++) {
            bool zin = (z >= zlo && z <= zhi);
            for (int y = nylo; y <= nyhi; y++) {
                int base = (z * GRID + y) * GRID;
                if (zin && y >= ylo && y <= yhi) {
                    // only new x-ranges
                    if (nxlo < xlo) seg(sstart[base + nxlo], sstart[base + xlo]);
                    if (nxhi > xhi) seg(sstart[base + xhi + 1], sstart[base + nxhi + 1]);
                } else {
                    seg(sstart[base + nxlo], sstart[base + nxhi + 1]);
                }
            }
        }
        xlo = nxlo; xhi = nxhi; ylo = nylo; yhi = nyhi; zlo = nzlo; zhi = nzhi;
        if (xlo == 0 && xhi == GRID - 1 && ylo == 0 && yhi == GRID - 1 &&
            zlo == 0 && zhi == GRID - 1) break;
    }

    const float r0 = 1.0f / (d0 + EPSW);
    const float r1 = 1.0f / (d1 + EPSW);
    const float r2 = 1.0f / (d2v + EPSW);
    const float s  = 1.0f / (r0 + r1 + r2);
    g_wp[(size_t)b * NQ + n] =
        make_float4(r0 * s, r1 * s,
                    __int_as_float(i0 | (i1 << 16)),
                    __int_as_float(i2));
}

// ---------------------------------------------------------------------------
// Kernel C: three_interpolate (unchanged — measured local floor ~33.5 us).
// ---------------------------------------------------------------------------
#define CG 4

__global__ void __launch_bounds__(256) interp_kernel(
    const float* __restrict__ feats,     // (B, C, M)
    float* __restrict__ out)             // (B, C, N)
{
    __shared__ float rowsT[MK * CG];     // 32 KB

    const int b  = blockIdx.y;
    const int c0 = blockIdx.x * CG;

    {
        const float* fp = feats + ((size_t)b * CC + c0) * MK;
#pragma unroll
        for (int it = 0; it < MK / 256; it++) {
            const int m = it * 256 + threadIdx.x;
            float a  = fp[m];
            float bb = fp[MK + m];
            float c  = fp[2 * MK + m];
            float d  = fp[3 * MK + m];
            *(float4*)&rowsT[m * 4] = make_float4(a, bb, c, d);
        }
    }
    __syncthreads();

    const float4* wp = (const float4*)&g_wp[(size_t)b * NQ];
    float* outp = out + ((size_t)b * CC + c0) * NQ;

    for (int it = 0; it < NQ / 1024; it++) {   // 8 iters
        const int n0 = it * 1024 + threadIdx.x * 4;

        float4 W0 = wp[n0 + 0];
        float4 W1 = wp[n0 + 1];
        float4 W2 = wp[n0 + 2];
        float4 W3 = wp[n0 + 3];

        int j[12];
        {
            unsigned pk0 = __float_as_uint(W0.z);
            unsigned pk1 = __float_as_uint(W1.z);
            unsigned pk2 = __float_as_uint(W2.z);
            unsigned pk3 = __float_as_uint(W3.z);
            j[0]  = pk0 & 0xFFFF; j[1]  = pk0 >> 16; j[2]  = __float_as_uint(W0.w);
            j[3]  = pk1 & 0xFFFF; j[4]  = pk1 >> 16; j[5]  = __float_as_uint(W1.w);
            j[6]  = pk2 & 0xFFFF; j[7]  = pk2 >> 16; j[8]  = __float_as_uint(W2.w);
            j[9]  = pk3 & 0xFFFF; j[10] = pk3 >> 16; j[11] = __float_as_uint(W3.w);
        }

        ulonglong2 f[12];
#pragma unroll
        for (int t = 0; t < 12; t++)
            f[t] = *(const ulonglong2*)&rowsT[j[t] * 4];

        float vq[4][4];
        const float4 Wv[4] = { W0, W1, W2, W3 };
#pragma unroll
        for (int q = 0; q < 4; q++) {
            float w0 = Wv[q].x, w1 = Wv[q].y;
            float w2 = 1.0f - w0 - w1;
            u64t w0p = pack2(w0, w0);
            u64t w1p = pack2(w1, w1);
            u64t w2p = pack2(w2, w2);
            u64t lo = fma2(w0p, f[3*q].x, fma2(w1p, f[3*q+1].x, mul2(w2p, f[3*q+2].x)));
            u64t hi = fma2(w0p, f[3*q].y, fma2(w1p, f[3*q+1].y, mul2(w2p, f[3*q+2].y)));
            unpack2(lo, vq[q][0], vq[q][1]);
            unpack2(hi, vq[q][2], vq[q][3]);
        }

#pragma unroll
        for (int c = 0; c < CG; c++) {
            float4 v = make_float4(vq[0][c], vq[1][c], vq[2][c], vq[3][c]);
            *(float4*)(outp + (size_t)c * NQ + n0) = v;
        }
    }
}

// ---------------------------------------------------------------------------
// Launch
// ---------------------------------------------------------------------------
extern "C" void kernel_launch(void* const* d_in, const int* in_sizes, int n_in,
                              void* d_out, int out_size)
{
    const float* unknown = (const float*)d_in[0];   // (8, 8192, 3)
    const float* known   = (const float*)d_in[1];   // (8, 2048, 3)
    const float* feats   = (const float*)d_in[2];   // (8, 256, 2048)
    float* out = (float*)d_out;                     // (8, 256, 8192)

    bin_kernel<<<dim3(BQ, 2), 512>>>(known, unknown);

    nn_kernel<<<dim3(NQ / 128, BQ), 128>>>();

    dim3 g2(CC / CG, BQ);
    interp_kernel<<<g2, 256>>>(feats, out);
}

// round 17
// speedup vs baseline: 4.1637x; 1.1677x over previous
#include <cuda_runtime.h>
#include <cuda_bf16.h>

#define BQ 8
#define NQ 8192
#define MK 2048
#define CC 256
#define EPSW 1e-8f
#define GRID 8
#define NCELL (GRID*GRID*GRID)   // 512
#define CELLH 0.125f

// Scratch
__device__ float4 g_pts[BQ * MK];              // binned known points (x,y,z,idx)
__device__ int    g_cellstart[BQ][NCELL + 1];  // known-point cell offsets
__device__ float4 g_qpts[BQ * NQ];             // binned queries (x,y,z,idx)
__device__ float4 g_wp[BQ * NQ];               // (w0,w1,i0|i1<<16,i2)

typedef unsigned long long u64t;
__device__ __forceinline__ u64t fma2(u64t a, u64t b, u64t c) {
    u64t d; asm("fma.rn.f32x2 %0, %1, %2, %3;" : "=l"(d) : "l"(a), "l"(b), "l"(c));
    return d;
}
__device__ __forceinline__ u64t mul2(u64t a, u64t b) {
    u64t d; asm("mul.rn.f32x2 %0, %1, %2;" : "=l"(d) : "l"(a), "l"(b));
    return d;
}
__device__ __forceinline__ u64t pack2(float lo, float hi) {
    u64t d; asm("mov.b64 %0, {%1, %2};" : "=l"(d) : "f"(lo), "f"(hi));
    return d;
}
__device__ __forceinline__ void unpack2(u64t v, float& lo, float& hi) {
    asm("mov.b64 {%0, %1}, %2;" : "=f"(lo), "=f"(hi) : "l"(v));
}

__device__ __forceinline__ int cell_of(float x, float y, float z) {
    int cx = min(GRID - 1, max(0, (int)(x * (float)GRID)));
    int cy = min(GRID - 1, max(0, (int)(y * (float)GRID)));
    int cz = min(GRID - 1, max(0, (int)(z * (float)GRID)));
    return (cz * GRID + cy) * GRID + cx;
}

// ---------------------------------------------------------------------------
// Kernel A: fused counting sort (known pts -> g_pts; queries -> g_qpts).
// Scatter order within a cell is nondeterministic — safe because the NN
// insert is lexicographic (order-independent).
// ---------------------------------------------------------------------------
__global__ void __launch_bounds__(512) bin_kernel(
    const float* __restrict__ known,     // (B, M, 3)
    const float* __restrict__ unknown)   // (B, N, 3)
{
    __shared__ int hist[NCELL];
    __shared__ int wsum[16];

    const int b = blockIdx.x;
    const int role = blockIdx.y;
    const int t = threadIdx.x;
    const int lane = t & 31, warp = t >> 5;

    hist[t] = 0;
    __syncthreads();

    if (role == 0) {
        const float* kb = known + (size_t)b * MK * 3;
#pragma unroll
        for (int k = 0; k < MK / 512; k++) {
            int m = k * 512 + t;
            atomicAdd(&hist[cell_of(kb[m*3], kb[m*3+1], kb[m*3+2])], 1);
        }
    } else {
        const float* ub = unknown + (size_t)b * NQ * 3;
#pragma unroll
        for (int k = 0; k < NQ / 512; k++) {
            int m = k * 512 + t;
            atomicAdd(&hist[cell_of(ub[m*3], ub[m*3+1], ub[m*3+2])], 1);
        }
    }
    __syncthreads();

    // block-wide exclusive scan of hist[512]
    int v = hist[t];
    int incl = v;
#pragma unroll
    for (int off = 1; off < 32; off <<= 1) {
        int u = __shfl_up_sync(0xFFFFFFFFu, incl, off);
        if (lane >= off) incl += u;
    }
    if (lane == 31) wsum[warp] = incl;
    __syncthreads();
    if (t < 16) {
        int w = wsum[t];
        int vv = w;
#pragma unroll
        for (int off = 1; off < 16; off <<= 1) {
            int u = __shfl_up_sync(0x0000FFFFu, vv, off);
            if (t >= off) vv += u;
        }
        wsum[t] = vv - w;
    }
    __syncthreads();
    int excl = wsum[warp] + incl - v;

    if (role == 0) {
        g_cellstart[b][t] = excl;
        if (t == 0) g_cellstart[b][NCELL] = MK;
    }
    __syncthreads();
    hist[t] = excl;          // scatter cursor
    __syncthreads();

    if (role == 0) {
        const float* kb = known + (size_t)b * MK * 3;
#pragma unroll
        for (int k = 0; k < MK / 512; k++) {
            int m = k * 512 + t;
            float x = kb[m*3], y = kb[m*3+1], z = kb[m*3+2];
            int pos = atomicAdd(&hist[cell_of(x, y, z)], 1);
            g_pts[(size_t)b * MK + pos] = make_float4(x, y, z, __int_as_float(m));
        }
    } else {
        const float* ub = unknown + (size_t)b * NQ * 3;
#pragma unroll
        for (int k = 0; k < NQ / 512; k++) {
            int m = k * 512 + t;
            float x = ub[m*3], y = ub[m*3+1], z = ub[m*3+2];
            int pos = atomicAdd(&hist[cell_of(x, y, z)], 1);
            g_qpts[(size_t)b * NQ + pos] = make_float4(x, y, z, __int_as_float(m));
        }
    }
}

// ---------------------------------------------------------------------------
// Kernel B: three_nn. Sorted-query lanes; radius-1 cube (no prune, lean
// common path) + expanding shells with (a) exact face-guard stop and
// (b) exact per-cell AABB distance prune: skip shell cells whose minimum
// squared distance to the query exceeds current d3^2 — any point inside is
// at least that far, so skipping is exact. Typical shell-2: ~90/98 cells
// pruned. EXACT d^2; lexicographic (d2, idx) insert.
// Block 128, grid (NQ/128, BQ) = 512 blocks.
// ---------------------------------------------------------------------------
__global__ void __launch_bounds__(128) nn_kernel()
{
    __shared__ float4 spts[MK];          // 32 KB
    __shared__ int    sstart[NCELL + 1];

    const int b = blockIdx.y;
    for (int i = threadIdx.x; i < MK; i += 128)
        spts[i] = g_pts[(size_t)b * MK + i];
    for (int i = threadIdx.x; i < NCELL + 1; i += 128)
        sstart[i] = g_cellstart[b][i];
    __syncthreads();

    const int qslot = blockIdx.x * 128 + threadIdx.x;
    float4 Q = g_qpts[(size_t)b * NQ + qslot];
    const float ux = Q.x, uy = Q.y, uz = Q.z;
    const int n = __float_as_int(Q.w);
    const int cx = min(GRID - 1, max(0, (int)(ux * (float)GRID)));
    const int cy = min(GRID - 1, max(0, (int)(uy * (float)GRID)));
    const int cz = min(GRID - 1, max(0, (int)(uz * (float)GRID)));

    float d0 = 1e30f, d1 = 1e30f, d2v = 1e30f;
    int   i0 = 0x7FFFFFFF, i1 = 0x7FFFFFFF, i2 = 0x7FFFFFFF;

    auto insert = [&](float d2, int m) {
        bool c0 = (d2 < d0) || (d2 == d0 && m < i0);
        bool c1 = (d2 < d1) || (d2 == d1 && m < i1);
        bool c2 = (d2 < d2v) || (d2 == d2v && m < i2);
        float t0 = c0 ? d2 : d0;
        float t1 = c0 ? d0 : (c1 ? d2 : d1);
        float t2 = c1 ? d1 : (c2 ? d2 : d2v);
        int   j0 = c0 ? m  : i0;
        int   j1 = c0 ? i0 : (c1 ? m  : i1);
        int   j2 = c1 ? i1 : (c2 ? m  : i2);
        d0 = t0; d1 = t1; d2v = t2;
        i0 = j0; i1 = j1; i2 = j2;
    };

    auto seg = [&](int p, int pend) {
        for (; p + 2 <= pend; p += 2) {
            float4 P0 = spts[p], P1 = spts[p + 1];
            float dx0 = P0.x - ux, dy0 = P0.y - uy, dz0 = P0.z - uz;
            float dx1 = P1.x - ux, dy1 = P1.y - uy, dz1 = P1.z - uz;
            float e0 = fmaf(dx0, dx0, fmaf(dy0, dy0, dz0 * dz0));
            float e1 = fmaf(dx1, dx1, fmaf(dy1, dy1, dz1 * dz1));
            insert(e0, __float_as_int(P0.w));
            insert(e1, __float_as_int(P1.w));
        }
        if (p < pend) {
            float4 P = spts[p];
            float dx = P.x - ux, dy = P.y - uy, dz = P.z - uz;
            insert(fmaf(dx, dx, fmaf(dy, dy, dz * dz)), __float_as_int(P.w));
        }
    };

    // exact guard^2 for processed box
    auto guard2 = [&](int xl, int xh, int yl, int yh, int zl, int zh) {
        float g = 1e15f;
        g = fminf(g, (xl > 0)        ? ux - (float)xl * CELLH        : 1e15f);
        g = fminf(g, (xh < GRID - 1) ? (float)(xh + 1) * CELLH - ux  : 1e15f);
        g = fminf(g, (yl > 0)        ? uy - (float)yl * CELLH        : 1e15f);
        g = fminf(g, (yh < GRID - 1) ? (float)(yh + 1) * CELLH - uy  : 1e15f);
        g = fminf(g, (zl > 0)        ? uz - (float)zl * CELLH        : 1e15f);
        g = fminf(g, (zh < GRID - 1) ? (float)(zh + 1) * CELLH - uz  : 1e15f);
        return g * g;
    };

    // exact min squared distance from query to cell (x,y,z) AABB
    auto cellmind2 = [&](int x, int y, int z) {
        float lx = (float)x * CELLH, hx = lx + CELLH;
        float ly = (float)y * CELLH, hy = ly + CELLH;
        float lz = (float)z * CELLH, hz = lz + CELLH;
        float dx = fmaxf(0.0f, fmaxf(lx - ux, ux - hx));
        float dy = fmaxf(0.0f, fmaxf(ly - uy, uy - hy));
        float dz = fmaxf(0.0f, fmaxf(lz - uz, uz - hz));
        return fmaf(dx, dx, fmaf(dy, dy, dz * dz));
    };

    // radius-1 cube: contiguous x-run per (z,y)
    int xlo = max(cx - 1, 0), xhi = min(cx + 1, GRID - 1);
    int ylo = max(cy - 1, 0), yhi = min(cy + 1, GRID - 1);
    int zlo = max(cz - 1, 0), zhi = min(cz + 1, GRID - 1);
    for (int z = zlo; z <= zhi; z++)
        for (int y = ylo; y <= yhi; y++) {
            int base = (z * GRID + y) * GRID;
            seg(sstart[base + xlo], sstart[base + xhi + 1]);
        }

    // expanding shells: exact guard stop + exact per-cell distance prune
#pragma unroll 1
    for (int s2 = 2; s2 <= GRID - 1; s2++) {
        if (d2v <= guard2(xlo, xhi, ylo, yhi, zlo, zhi)) break;
        int nxlo = max(cx - s2, 0), nxhi = min(cx + s2, GRID - 1);
        int nylo = max(cy - s2, 0), nyhi = min(cy + s2, GRID - 1);
        int nzlo = max(cz - s2, 0), nzhi = min(cz + s2, GRID - 1);
        for (int z = nzlo; z <= nzhi; z++) {
            bool zin = (z >= zlo && z <= zhi);
            for (int y = nylo; y <= nyhi; y++) {
                bool inprev = zin && (y >= ylo && y <= yhi);
                int base = (z * GRID + y) * GRID;
                for (int x = nxlo; x <= nxhi; x++) {
                    if (inprev && x >= xlo && x <= xhi) continue;  // done before
                    if (cellmind2(x, y, z) > d2v) continue;        // exact prune
                    seg(sstart[base + x], sstart[base + x + 1]);
                }
            }
        }
        xlo = nxlo; xhi = nxhi; ylo = nylo; yhi = nyhi; zlo = nzlo; zhi = nzhi;
        if (xlo == 0 && xhi == GRID - 1 && ylo == 0 && yhi == GRID - 1 &&
            zlo == 0 && zhi == GRID - 1) break;
    }

    const float r0 = 1.0f / (d0 + EPSW);
    const float r1 = 1.0f / (d1 + EPSW);
    const float r2 = 1.0f / (d2v + EPSW);
    const float s  = 1.0f / (r0 + r1 + r2);
    g_wp[(size_t)b * NQ + n] =
        make_float4(r0 * s, r1 * s,
                    __int_as_float(i0 | (i1 << 16)),
                    __int_as_float(i2));
}

// ---------------------------------------------------------------------------
// Kernel C: three_interpolate (unchanged — measured local floor ~33.5 us).
// ---------------------------------------------------------------------------
#define CG 4

__global__ void __launch_bounds__(256) interp_kernel(
    const float* __restrict__ feats,     // (B, C, M)
    float* __restrict__ out)             // (B, C, N)
{
    __shared__ float rowsT[MK * CG];     // 32 KB

    const int b  = blockIdx.y;
    const int c0 = blockIdx.x * CG;

    {
        const float* fp = feats + ((size_t)b * CC + c0) * MK;
#pragma unroll
        for (int it = 0; it < MK / 256; it++) {
            const int m = it * 256 + threadIdx.x;
            float a  = fp[m];
            float bb = fp[MK + m];
            float c  = fp[2 * MK + m];
            float d  = fp[3 * MK + m];
            *(float4*)&rowsT[m * 4] = make_float4(a, bb, c, d);
        }
    }
    __syncthreads();

    const float4* wp = (const float4*)&g_wp[(size_t)b * NQ];
    float* outp = out + ((size_t)b * CC + c0) * NQ;

    for (int it = 0; it < NQ / 1024; it++) {   // 8 iters
        const int n0 = it * 1024 + threadIdx.x * 4;

        float4 W0 = wp[n0 + 0];
        float4 W1 = wp[n0 + 1];
        float4 W2 = wp[n0 + 2];
        float4 W3 = wp[n0 + 3];

        int j[12];
        {
            unsigned pk0 = __float_as_uint(W0.z);
            unsigned pk1 = __float_as_uint(W1.z);
            unsigned pk2 = __float_as_uint(W2.z);
            unsigned pk3 = __float_as_uint(W3.z);
            j[0]  = pk0 & 0xFFFF; j[1]  = pk0 >> 16; j[2]  = __float_as_uint(W0.w);
            j[3]  = pk1 & 0xFFFF; j[4]  = pk1 >> 16; j[5]  = __float_as_uint(W1.w);
            j[6]  = pk2 & 0xFFFF; j[7]  = pk2 >> 16; j[8]  = __float_as_uint(W2.w);
            j[9]  = pk3 & 0xFFFF; j[10] = pk3 >> 16; j[11] = __float_as_uint(W3.w);
        }

        ulonglong2 f[12];
#pragma unroll
        for (int t = 0; t < 12; t++)
            f[t] = *(const ulonglong2*)&rowsT[j[t] * 4];

        float vq[4][4];
        const float4 Wv[4] = { W0, W1, W2, W3 };
#pragma unroll
        for (int q = 0; q < 4; q++) {
            float w0 = Wv[q].x, w1 = Wv[q].y;
            float w2 = 1.0f - w0 - w1;
            u64t w0p = pack2(w0, w0);
            u64t w1p = pack2(w1, w1);
            u64t w2p = pack2(w2, w2);
            u64t lo = fma2(w0p, f[3*q].x, fma2(w1p, f[3*q+1].x, mul2(w2p, f[3*q+2].x)));
            u64t hi = fma2(w0p, f[3*q].y, fma2(w1p, f[3*q+1].y, mul2(w2p, f[3*q+2].y)));
            unpack2(lo, vq[q][0], vq[q][1]);
            unpack2(hi, vq[q][2], vq[q][3]);
        }

#pragma unroll
        for (int c = 0; c < CG; c++) {
            float4 v = make_float4(vq[0][c], vq[1][c], vq[2][c], vq[3][c]);
            *(float4*)(outp + (size_t)c * NQ + n0) = v;
        }
    }
}

// ---------------------------------------------------------------------------
// Launch
// ---------------------------------------------------------------------------
extern "C" void kernel_launch(void* const* d_in, const int* in_sizes, int n_in,
                              void* d_out, int out_size)
{
    const float* unknown = (const float*)d_in[0];   // (8, 8192, 3)
    const float* known   = (const float*)d_in[1];   // (8, 2048, 3)
    const float* feats   = (const float*)d_in[2];   // (8, 256, 2048)
    float* out = (float*)d_out;                     // (8, 256, 8192)

    bin_kernel<<<dim3(BQ, 2), 512>>>(known, unknown);

    nn_kernel<<<dim3(NQ / 128, BQ), 128>>>();

    dim3 g2(CC / CG, BQ);
    interp_kernel<<<g2, 256>>>(feats, out);
}